// round 15
// baseline (speedup 1.0000x reference)
#include <cuda_runtime.h>
#include <cuda_bf16.h>
#include <math.h>

#define N_ROWS 8192
#define D_DIM  128
#define STAT_VB 1024        // virtual stats blocks (8 rows each)
#define NTILES  2080        // upper triangle: 64*65/2
#define GRID 592            // 148 SMs x 4 resident
#define PB 24               // smem pitch in bf16 (48B)
#define SQ2 1.41421356237f

// ---------------- device scratch ----------------
__device__ float   d_vsum[2][D_DIM];
__device__ float4  d_part[STAT_VB];     // {focal, graph, sn0, sn1}
__device__ float   d_pc[STAT_VB];       // count of label-1 rows
__device__ double  d_cross;             // ordered cross-pair margin sum
__device__ unsigned d_done;

struct SmemS {
    float v[8][D_DIM];
    float g[8][D_DIM];
    float sn[2];
    float focal, graph;
    int   lab[8];
};
struct SmemT {
    __nv_bfloat16 A[128 * PB];
    __nv_bfloat16 B[128 * PB];
    float    redw[8];
    double   sd[5][8];
    double   s[256];
};

__device__ __forceinline__ float warp_sum(float v) {
    #pragma unroll
    for (int o = 16; o > 0; o >>= 1) v += __shfl_xor_sync(0xffffffffu, v, o);
    return v;
}
__device__ __forceinline__ double warp_sum_d(double v) {
    #pragma unroll
    for (int o = 16; o > 0; o >>= 1) v += __shfl_xor_sync(0xffffffffu, v, o);
    return v;
}

// exact fp32 recheck on ORIGINAL rows; norms computed inline
__device__ __noinline__ float rare_pair(const float* __restrict__ feat,
                                        const float* __restrict__ tgt,
                                        int gi, int gj) {
    if (gi == gj) return 0.0f;
    float ti = tgt[gi], tj = tgt[gj];
    if ((ti > 0.5f) == (tj > 0.5f)) return 0.0f;   // same label: not a cross pair
    const float* A = feat + (size_t)gi * D_DIM;
    const float* B = feat + (size_t)gj * D_DIM;
    float dot = 0.0f, na = 0.0f, nb = 0.0f;
    #pragma unroll 4
    for (int d = 0; d < D_DIM; ++d) {
        float a = A[d], b = B[d];
        dot += a * b; na += a * a; nb += b * b;
    }
    float sq = fmaxf(na + nb - 2.0f * dot, 0.0f);
    float t = 1.0f - sqrtf(sq);
    return (t > 0.0f) ? t * t : 0.0f;
}

// ---------------- single fused kernel, no inter-phase barrier ----------------
__global__ void __launch_bounds__(256, 4) fused_kernel(
    const float* __restrict__ preds,
    const float* __restrict__ targets,
    const float* __restrict__ features,
    const float* __restrict__ gfeat,
    float* __restrict__ out)
{
    __shared__ union { SmemS p; SmemT c; } sm;
    __shared__ unsigned s_ticket;

    int tid = threadIdx.x;
    int bid = blockIdx.x;
    int warp = tid >> 5, lane = tid & 31;

    // ============ stats pass (row-parallel; independent of tiles) ============
    for (int vb = bid; vb < STAT_VB; vb += GRID) {
        // init shared accumulators FIRST, then sync before any shared atomics
        if (tid == 254) { sm.p.sn[0] = 0.0f; sm.p.sn[1] = 0.0f; }
        if (tid == 255) { sm.p.focal = 0.0f; sm.p.graph = 0.0f; }

        int i = vb * 8 + warp;

        float4 f = *(const float4*)(features + (size_t)i * D_DIM + lane * 4);
        float c  = f.x*f.x + f.y*f.y + f.z*f.z + f.w*f.w;
        float nsq = warp_sum(c);

        float4 ga = *(const float4*)(gfeat + (size_t)i * D_DIM + lane * 4);

        float tgt = targets[i];
        int lab = (tgt > 0.5f) ? 1 : 0;
        if (lane == 0) sm.p.lab[warp] = lab;

        sm.p.v[warp][lane * 4 + 0] = f.x;
        sm.p.v[warp][lane * 4 + 1] = f.y;
        sm.p.v[warp][lane * 4 + 2] = f.z;
        sm.p.v[warp][lane * 4 + 3] = f.w;
        *(float4*)&sm.p.g[warp][lane * 4] = ga;
        __syncthreads();   // init + stores visible before atomics/reads

        if (lane == 0) atomicAdd(&sm.p.sn[lab], nsq);
        if (lane == 0) {
            float p = preds[i];
            float bce = fmaxf(p, 0.0f) - p * tgt + log1pf(expf(-fabsf(p)));
            float pt = expf(-bce);
            float om = 1.0f - pt;
            atomicAdd(&sm.p.focal, 0.25f * om * om * bce);
        }

        if (i >= 1) {
            float4 gb;
            if (warp == 0)
                gb = *(const float4*)(gfeat + (size_t)(i - 1) * D_DIM + lane * 4);
            else
                gb = *(const float4*)&sm.p.g[warp - 1][lane * 4];
            float dx = ga.x - gb.x, dy = ga.y - gb.y;
            float dz = ga.z - gb.z, dw = ga.w - gb.w;
            float ds = warp_sum(dx*dx + dy*dy + dz*dz + dw*dw);
            if (lane == 0) atomicAdd(&sm.p.graph, sqrtf(ds));
        }

        {
            int cls = tid >> 7, comp = tid & 127;
            float sum = 0.0f;
            #pragma unroll
            for (int w = 0; w < 8; ++w)
                if (sm.p.lab[w] == cls) sum += sm.p.v[w][comp];
            if (sum != 0.0f) atomicAdd(&d_vsum[cls][comp], sum);
        }
        __syncthreads();   // all shared atomics complete before leader reads
        if (tid == 0) {
            int c1 = 0;
            #pragma unroll
            for (int w = 0; w < 8; ++w) c1 += sm.p.lab[w];
            d_part[vb] = make_float4(sm.p.focal, sm.p.graph, sm.p.sn[0], sm.p.sn[1]);
            d_pc[vb] = (float)c1;
        }
        __syncthreads();   // leader done reading before next-iter re-init
    }

    // ============ all-pairs screen over upper-triangle tiles ============
    int wid = warp;
    int g = lane >> 2, t = lane & 3;
    int r0 = (wid & 3) * 32;
    int c0 = (wid >> 2) * 64;

    float lsum = 0.0f;

    for (int k = bid; k < NTILES; k += GRID) {
        // invert triangular index: S(tr) = tr*(129-tr)/2
        int tr = (int)((129.0f - sqrtf(129.0f * 129.0f - 8.0f * (float)k)) * 0.5f);
        while ((tr + 1) * (129 - (tr + 1)) / 2 <= k) ++tr;
        while (tr * (129 - tr) / 2 > k) --tr;
        int tc = tr + (k - tr * (129 - tr) / 2);
        int row0 = tr * 128, col0 = tc * 128;
        float wgt = (tr == tc) ? 1.0f : 2.0f;

        // ---- in-tile conversion: 1 row per thread ----
        {
            int side = tid >> 7;            // 0 = A row, 1 = B row
            int r = tid & 127;
            int grow = (side ? col0 : row0) + r;
            const float* F = features + (size_t)grow * D_DIM;
            float4 x0 = *(const float4*)(F);
            float4 x1 = *(const float4*)(F + 4);
            float4 x2 = *(const float4*)(F + 8);
            float lab = targets[grow];
            float nsq12 = x0.x*x0.x + x0.y*x0.y + x0.z*x0.z + x0.w*x0.w
                        + x1.x*x1.x + x1.y*x1.y + x1.z*x1.z + x1.w*x1.w
                        + x2.x*x2.x + x2.y*x2.y + x2.z*x2.z + x2.w*x2.w;
            float sgn = side ? SQ2 : -SQ2;

            __nv_bfloat162 p0 = __floats2bfloat162_rn(sgn*x0.x, sgn*x0.y);
            __nv_bfloat162 p1 = __floats2bfloat162_rn(sgn*x0.z, sgn*x0.w);
            __nv_bfloat162 p2 = __floats2bfloat162_rn(sgn*x1.x, sgn*x1.y);
            __nv_bfloat162 p3 = __floats2bfloat162_rn(sgn*x1.z, sgn*x1.w);
            __nv_bfloat162 p4 = __floats2bfloat162_rn(sgn*x2.x, sgn*x2.y);
            __nv_bfloat162 p5 = __floats2bfloat162_rn(sgn*x2.z, sgn*x2.w);
            __nv_bfloat162 p6 = side ? __floats2bfloat162_rn(1.0f, nsq12)
                                     : __floats2bfloat162_rn(nsq12, 1.0f);
            __nv_bfloat162 p7 = (lab > 0.5f) ? __floats2bfloat162_rn(0.0f, 16.0f)
                                             : __floats2bfloat162_rn(16.0f, 0.0f);
            __nv_bfloat16* dst = (side ? sm.c.B : sm.c.A) + r * PB;
            uint4 lo, hi;
            lo.x = *(unsigned*)&p0; lo.y = *(unsigned*)&p1;
            lo.z = *(unsigned*)&p2; lo.w = *(unsigned*)&p3;
            hi.x = *(unsigned*)&p4; hi.y = *(unsigned*)&p5;
            hi.z = *(unsigned*)&p6; hi.w = *(unsigned*)&p7;
            *(uint4*)(dst)     = lo;
            *(uint4*)(dst + 8) = hi;
        }
        __syncthreads();

        // ---- A fragments ----
        unsigned a[2][4];
        #pragma unroll
        for (int rb = 0; rb < 2; ++rb) {
            const __nv_bfloat16* base = sm.c.A + (r0 + rb * 16 + g) * PB + t * 2;
            a[rb][0] = *(const unsigned*)(base);
            a[rb][1] = *(const unsigned*)(base + 8 * PB);
            a[rb][2] = *(const unsigned*)(base + 8);
            a[rb][3] = *(const unsigned*)(base + 8 * PB + 8);
        }

        unsigned fmask = 0u;
        #pragma unroll
        for (int cb = 0; cb < 8; ++cb) {
            const __nv_bfloat16* bb = sm.c.B + (c0 + cb * 8 + g) * PB + t * 2;
            unsigned b0 = *(const unsigned*)(bb);
            unsigned b1 = *(const unsigned*)(bb + 8);
            #pragma unroll
            for (int rb = 0; rb < 2; ++rb) {
                float d0, d1, d2, d3;
                asm("mma.sync.aligned.m16n8k16.row.col.f32.bf16.bf16.f32 "
                    "{%0,%1,%2,%3},{%4,%5,%6,%7},{%8,%9},{%10,%10,%10,%10};"
                    : "=f"(d0), "=f"(d1), "=f"(d2), "=f"(d3)
                    : "r"(a[rb][0]), "r"(a[rb][1]), "r"(a[rb][2]), "r"(a[rb][3]),
                      "r"(b0), "r"(b1), "f"(0.0f));
                float mn = fminf(fminf(d0, d1), fminf(d2, d3));
                if (mn < 1.5f) fmask |= 1u << (cb * 2 + rb);
            }
        }

        if (fmask) {   // ~100 pairs chip-wide survive (12-dim + label screen)
            #pragma unroll 1
            while (fmask) {
                int b = __ffs(fmask) - 1;
                fmask &= fmask - 1;
                int cb = b >> 1, rb = b & 1;
                int gib = row0 + r0 + rb * 16 + g;
                int gjb = col0 + c0 + cb * 8 + t * 2;
                #pragma unroll 1
                for (int q = 0; q < 4; ++q) {
                    int gi = gib + (q >> 1) * 8;
                    int gj = gjb + (q & 1);
                    lsum += wgt * rare_pair(features, targets, gi, gj);
                }
            }
        }
        __syncthreads();
    }

    // ============ reduce + ticket finalize ============
    lsum = warp_sum(lsum);
    if (lane == 0) sm.c.redw[wid] = lsum;
    __syncthreads();
    if (tid == 0) {
        float s = 0.0f;
        #pragma unroll
        for (int w = 0; w < 8; ++w) s += sm.c.redw[w];
        if (s != 0.0f) atomicAdd(&d_cross, (double)s);
        __threadfence();
        s_ticket = atomicAdd(&d_done, 1u);
    }
    __syncthreads();

    if (s_ticket == GRID - 1) {
        if (tid == 0) __threadfence();
        __syncthreads();

        double pf = 0.0, pg = 0.0, p0 = 0.0, p1 = 0.0, pc = 0.0;
        #pragma unroll
        for (int kk = 0; kk < STAT_VB / 256; ++kk) {
            float4 p = d_part[tid + kk * 256];
            pf += p.x; pg += p.y; p0 += p.z; p1 += p.w;
            pc += d_pc[tid + kk * 256];
        }
        pf = warp_sum_d(pf); pg = warp_sum_d(pg);
        p0 = warp_sum_d(p0); p1 = warp_sum_d(p1);
        pc = warp_sum_d(pc);
        if (lane == 0) {
            sm.c.sd[0][wid] = pf; sm.c.sd[1][wid] = pg;
            sm.c.sd[2][wid] = p0; sm.c.sd[3][wid] = p1;
            sm.c.sd[4][wid] = pc;
        }

        int cls = tid >> 7, comp = tid & 127;
        double v = (double)d_vsum[cls][comp];
        sm.c.s[tid] = v * v;
        __syncthreads();
        for (int st = 64; st > 0; st >>= 1) {
            if (comp < st) sm.c.s[tid] += sm.c.s[tid + st];
            __syncthreads();
        }
        if (tid == 0) {
            double focal_s = 0.0, graph_s = 0.0, sn0 = 0.0, sn1 = 0.0, c1 = 0.0;
            #pragma unroll
            for (int w = 0; w < 8; ++w) {
                focal_s += sm.c.sd[0][w]; graph_s += sm.c.sd[1][w];
                sn0 += sm.c.sd[2][w]; sn1 += sm.c.sd[3][w];
                c1 += sm.c.sd[4][w];
            }
            double vn0 = sm.c.s[0], vn1 = sm.c.s[128];
            double dn1 = c1, dn0 = (double)N_ROWS - c1;
            double same = 2.0 * (dn0 * sn0 - vn0) + 2.0 * (dn1 * sn1 - vn1);
            double NN = (double)N_ROWS * (double)N_ROWS;
            double contrast = (same + d_cross) / NN;   // ordered-pair cross sum
            double focal = focal_s / (double)N_ROWS;
            double graph = 0.1 * graph_s / (double)(N_ROWS - 1);
            out[0] = (float)(focal + contrast + graph);
            d_cross = 0.0;
            d_done  = 0u;
        }
        d_vsum[cls][comp] = 0.0f;
    }
}

// ---------------- launch ----------------
extern "C" void kernel_launch(void* const* d_in, const int* in_sizes, int n_in,
                              void* d_out, int out_size) {
    const float* preds    = (const float*)d_in[0];
    const float* targets  = (const float*)d_in[1];
    const float* features = (const float*)d_in[2];
    const float* gfeat    = (const float*)d_in[3];
    float* out = (float*)d_out;

    fused_kernel<<<GRID, 256>>>(preds, targets, features, gfeat, out);
}

// round 16
// speedup vs baseline: 1.1625x; 1.1625x over previous
#include <cuda_runtime.h>
#include <cuda_bf16.h>
#include <math.h>

#define N_ROWS 8192
#define D_DIM  128
#define STAT_VB 1024          // virtual stats blocks (8 rows each)
#define STATS_BLOCKS 148
#define NT_SIDE 32            // 8192 / 256
#define NTILES  528           // triangle: 32*33/2
#define GRID_TOT (NTILES + STATS_BLOCKS)   // 676
#define PB 24                 // smem pitch in bf16 (48B): conflict-free frags
#define SQ2 1.41421356237f
#define THRESH 2.0f

// ---------------- device scratch ----------------
__device__ float   d_vsum[2][D_DIM];
__device__ float4  d_part[STAT_VB];     // {focal, graph, sn0, sn1}
__device__ float   d_pc[STAT_VB];       // count of label-1 rows
__device__ double  d_cross;             // ordered cross-pair margin sum
__device__ unsigned d_done;

struct SmemS {
    float v[8][D_DIM];
    float g[8][D_DIM];
    float sn[2];
    float focal, graph;
    int   lab[8];
};
struct SmemT {
    __nv_bfloat16 A[256 * PB];
    __nv_bfloat16 B[256 * PB];
    float    redw[8];
    double   sd[5][8];
    double   s[256];
};

__device__ __forceinline__ float warp_sum(float v) {
    #pragma unroll
    for (int o = 16; o > 0; o >>= 1) v += __shfl_xor_sync(0xffffffffu, v, o);
    return v;
}
__device__ __forceinline__ double warp_sum_d(double v) {
    #pragma unroll
    for (int o = 16; o > 0; o >>= 1) v += __shfl_xor_sync(0xffffffffu, v, o);
    return v;
}

// exact fp32 recheck on ORIGINAL rows; norms computed inline
__device__ __noinline__ float rare_pair(const float* __restrict__ feat,
                                        const float* __restrict__ tgt,
                                        int gi, int gj) {
    if (gi == gj) return 0.0f;
    float ti = tgt[gi], tj = tgt[gj];
    if ((ti > 0.5f) == (tj > 0.5f)) return 0.0f;
    const float* A = feat + (size_t)gi * D_DIM;
    const float* B = feat + (size_t)gj * D_DIM;
    float dot = 0.0f, na = 0.0f, nb = 0.0f;
    #pragma unroll 4
    for (int d = 0; d < D_DIM; ++d) {
        float a = A[d], b = B[d];
        dot += a * b; na += a * a; nb += b * b;
    }
    float sq = fmaxf(na + nb - 2.0f * dot, 0.0f);
    float t = 1.0f - sqrtf(sq);
    return (t > 0.0f) ? t * t : 0.0f;
}

// build one bf16 screen row (12 feat dims + norm-aux + label-aux = 16)
__device__ __forceinline__ void make_row(const float* __restrict__ F,
                                         float lab, float sgn, int sideB,
                                         __nv_bfloat16* dst) {
    float4 x0 = *(const float4*)(F);
    float4 x1 = *(const float4*)(F + 4);
    float4 x2 = *(const float4*)(F + 8);
    float nsq12 = x0.x*x0.x + x0.y*x0.y + x0.z*x0.z + x0.w*x0.w
                + x1.x*x1.x + x1.y*x1.y + x1.z*x1.z + x1.w*x1.w
                + x2.x*x2.x + x2.y*x2.y + x2.z*x2.z + x2.w*x2.w;
    __nv_bfloat162 p0 = __floats2bfloat162_rn(sgn*x0.x, sgn*x0.y);
    __nv_bfloat162 p1 = __floats2bfloat162_rn(sgn*x0.z, sgn*x0.w);
    __nv_bfloat162 p2 = __floats2bfloat162_rn(sgn*x1.x, sgn*x1.y);
    __nv_bfloat162 p3 = __floats2bfloat162_rn(sgn*x1.z, sgn*x1.w);
    __nv_bfloat162 p4 = __floats2bfloat162_rn(sgn*x2.x, sgn*x2.y);
    __nv_bfloat162 p5 = __floats2bfloat162_rn(sgn*x2.z, sgn*x2.w);
    __nv_bfloat162 p6 = sideB ? __floats2bfloat162_rn(1.0f, nsq12)
                              : __floats2bfloat162_rn(nsq12, 1.0f);
    __nv_bfloat162 p7 = (lab > 0.5f) ? __floats2bfloat162_rn(0.0f, 16.0f)
                                     : __floats2bfloat162_rn(16.0f, 0.0f);
    uint4 lo, hi;
    lo.x = *(unsigned*)&p0; lo.y = *(unsigned*)&p1;
    lo.z = *(unsigned*)&p2; lo.w = *(unsigned*)&p3;
    hi.x = *(unsigned*)&p4; hi.y = *(unsigned*)&p5;
    hi.z = *(unsigned*)&p6; hi.w = *(unsigned*)&p7;
    *(uint4*)(dst)     = lo;
    *(uint4*)(dst + 8) = hi;
}

// ---------------- single launch: specialized blocks, no barrier -------------
__global__ void __launch_bounds__(256, 4) fused_kernel(
    const float* __restrict__ preds,
    const float* __restrict__ targets,
    const float* __restrict__ features,
    const float* __restrict__ gfeat,
    float* __restrict__ out)
{
    __shared__ union { SmemS p; SmemT c; } sm;
    __shared__ unsigned s_ticket;

    int tid = threadIdx.x;
    int bid = blockIdx.x;
    int warp = tid >> 5, lane = tid & 31;

    float lsum = 0.0f;

    if (bid < NTILES) {
        // ================= tile block: one 256x256 triangle tile =============
        // invert triangular index: C(tr) = tr*(65-tr)/2
        int k = bid;
        int tr = (int)((65.0f - sqrtf(65.0f * 65.0f - 8.0f * (float)k)) * 0.5f);
        if (tr > NT_SIDE - 1) tr = NT_SIDE - 1;
        if (tr < 0) tr = 0;
        while (tr < NT_SIDE - 1 && (tr + 1) * (65 - (tr + 1)) / 2 <= k) ++tr;
        while (tr > 0 && tr * (65 - tr) / 2 > k) --tr;
        int tc = tr + (k - tr * (65 - tr) / 2);
        int row0 = tr * 256, col0 = tc * 256;
        float wgt = (tr == tc) ? 1.0f : 2.0f;

        // ---- in-tile conversion: 2 rows/thread (one each side) ----
        {
            int ga = row0 + tid;
            int gb = col0 + tid;
            float la = targets[ga];
            float lb = targets[gb];
            make_row(features + (size_t)ga * D_DIM, la, -SQ2, 0, sm.c.A + tid * PB);
            make_row(features + (size_t)gb * D_DIM, lb,  SQ2, 1, sm.c.B + tid * PB);
        }
        __syncthreads();

        // ---- warp covers 32 rows x 256 cols ----
        int g = lane >> 2, t = lane & 3;
        int r0 = warp * 32;

        unsigned a[2][4];
        #pragma unroll
        for (int rb = 0; rb < 2; ++rb) {
            const __nv_bfloat16* base = sm.c.A + (r0 + rb * 16 + g) * PB + t * 2;
            a[rb][0] = *(const unsigned*)(base);
            a[rb][1] = *(const unsigned*)(base + 8 * PB);
            a[rb][2] = *(const unsigned*)(base + 8);
            a[rb][3] = *(const unsigned*)(base + 8 * PB + 8);
        }

        unsigned long long fmask = 0ull;
        #pragma unroll 8
        for (int cb = 0; cb < 32; ++cb) {
            const __nv_bfloat16* bb = sm.c.B + (cb * 8 + g) * PB + t * 2;
            unsigned b0 = *(const unsigned*)(bb);
            unsigned b1 = *(const unsigned*)(bb + 8);
            #pragma unroll
            for (int rb = 0; rb < 2; ++rb) {
                float d0, d1, d2, d3;
                asm("mma.sync.aligned.m16n8k16.row.col.f32.bf16.bf16.f32 "
                    "{%0,%1,%2,%3},{%4,%5,%6,%7},{%8,%9},{%10,%10,%10,%10};"
                    : "=f"(d0), "=f"(d1), "=f"(d2), "=f"(d3)
                    : "r"(a[rb][0]), "r"(a[rb][1]), "r"(a[rb][2]), "r"(a[rb][3]),
                      "r"(b0), "r"(b1), "f"(0.0f));
                float mn = fminf(fminf(d0, d1), fminf(d2, d3));
                if (mn < THRESH) fmask |= 1ull << (cb * 2 + rb);
            }
        }

        if (fmask) {   // ~100 quads chip-wide survive the 12-dim+label screen
            #pragma unroll 1
            while (fmask) {
                int b = __ffsll((long long)fmask) - 1;
                fmask &= fmask - 1;
                int cb = b >> 1, rb = b & 1;
                int gib = row0 + r0 + rb * 16 + g;
                int gjb = col0 + cb * 8 + t * 2;
                #pragma unroll 1
                for (int q = 0; q < 4; ++q) {
                    int gi = gib + (q >> 1) * 8;
                    int gj = gjb + (q & 1);
                    lsum += wgt * rare_pair(features, targets, gi, gj);
                }
            }
        }
        __syncthreads();   // done with sm.c tiles before finalize may reuse
    } else {
        // ================= stats block: ~7 virtual blocks =====================
        int sidx = bid - NTILES;           // 0..147
        for (int vb = sidx; vb < STAT_VB; vb += STATS_BLOCKS) {
            if (tid == 254) { sm.p.sn[0] = 0.0f; sm.p.sn[1] = 0.0f; }
            if (tid == 255) { sm.p.focal = 0.0f; sm.p.graph = 0.0f; }

            int i = vb * 8 + warp;

            float4 f = *(const float4*)(features + (size_t)i * D_DIM + lane * 4);
            float c  = f.x*f.x + f.y*f.y + f.z*f.z + f.w*f.w;
            float nsq = warp_sum(c);

            float4 ga = *(const float4*)(gfeat + (size_t)i * D_DIM + lane * 4);

            float tgt = targets[i];
            int lab = (tgt > 0.5f) ? 1 : 0;
            if (lane == 0) sm.p.lab[warp] = lab;

            sm.p.v[warp][lane * 4 + 0] = f.x;
            sm.p.v[warp][lane * 4 + 1] = f.y;
            sm.p.v[warp][lane * 4 + 2] = f.z;
            sm.p.v[warp][lane * 4 + 3] = f.w;
            *(float4*)&sm.p.g[warp][lane * 4] = ga;
            __syncthreads();   // init + stores visible before atomics/reads

            if (lane == 0) atomicAdd(&sm.p.sn[lab], nsq);
            if (lane == 0) {
                float p = preds[i];
                float bce = fmaxf(p, 0.0f) - p * tgt + log1pf(expf(-fabsf(p)));
                float pt = expf(-bce);
                float om = 1.0f - pt;
                atomicAdd(&sm.p.focal, 0.25f * om * om * bce);
            }

            if (i >= 1) {
                float4 gb;
                if (warp == 0)
                    gb = *(const float4*)(gfeat + (size_t)(i - 1) * D_DIM + lane * 4);
                else
                    gb = *(const float4*)&sm.p.g[warp - 1][lane * 4];
                float dx = ga.x - gb.x, dy = ga.y - gb.y;
                float dz = ga.z - gb.z, dw = ga.w - gb.w;
                float ds = warp_sum(dx*dx + dy*dy + dz*dz + dw*dw);
                if (lane == 0) atomicAdd(&sm.p.graph, sqrtf(ds));
            }

            {
                int cls = tid >> 7, comp = tid & 127;
                float sum = 0.0f;
                #pragma unroll
                for (int w = 0; w < 8; ++w)
                    if (sm.p.lab[w] == cls) sum += sm.p.v[w][comp];
                if (sum != 0.0f) atomicAdd(&d_vsum[cls][comp], sum);
            }
            __syncthreads();   // shared atomics complete before leader reads
            if (tid == 0) {
                int c1 = 0;
                #pragma unroll
                for (int w = 0; w < 8; ++w) c1 += sm.p.lab[w];
                d_part[vb] = make_float4(sm.p.focal, sm.p.graph,
                                         sm.p.sn[0], sm.p.sn[1]);
                d_pc[vb] = (float)c1;
            }
            __syncthreads();   // leader done before next-iter re-init
        }
    }

    // ============ common: reduce + ticket finalize ============
    lsum = warp_sum(lsum);
    if (lane == 0) sm.c.redw[warp] = lsum;
    __syncthreads();
    if (tid == 0) {
        float s = 0.0f;
        #pragma unroll
        for (int w = 0; w < 8; ++w) s += sm.c.redw[w];
        if (s != 0.0f) atomicAdd(&d_cross, (double)s);
        __threadfence();
        s_ticket = atomicAdd(&d_done, 1u);
    }
    __syncthreads();

    if (s_ticket == GRID_TOT - 1) {
        if (tid == 0) __threadfence();
        __syncthreads();

        double pf = 0.0, pg = 0.0, p0 = 0.0, p1 = 0.0, pc = 0.0;
        #pragma unroll
        for (int kk = 0; kk < STAT_VB / 256; ++kk) {
            float4 p = d_part[tid + kk * 256];
            pf += p.x; pg += p.y; p0 += p.z; p1 += p.w;
            pc += d_pc[tid + kk * 256];
        }
        pf = warp_sum_d(pf); pg = warp_sum_d(pg);
        p0 = warp_sum_d(p0); p1 = warp_sum_d(p1);
        pc = warp_sum_d(pc);
        if (lane == 0) {
            sm.c.sd[0][warp] = pf; sm.c.sd[1][warp] = pg;
            sm.c.sd[2][warp] = p0; sm.c.sd[3][warp] = p1;
            sm.c.sd[4][warp] = pc;
        }

        int cls = tid >> 7, comp = tid & 127;
        double v = (double)d_vsum[cls][comp];
        sm.c.s[tid] = v * v;
        __syncthreads();
        for (int st = 64; st > 0; st >>= 1) {
            if (comp < st) sm.c.s[tid] += sm.c.s[tid + st];
            __syncthreads();
        }
        if (tid == 0) {
            double focal_s = 0.0, graph_s = 0.0, sn0 = 0.0, sn1 = 0.0, c1 = 0.0;
            #pragma unroll
            for (int w = 0; w < 8; ++w) {
                focal_s += sm.c.sd[0][w]; graph_s += sm.c.sd[1][w];
                sn0 += sm.c.sd[2][w]; sn1 += sm.c.sd[3][w];
                c1 += sm.c.sd[4][w];
            }
            double vn0 = sm.c.s[0], vn1 = sm.c.s[128];
            double dn1 = c1, dn0 = (double)N_ROWS - c1;
            double same = 2.0 * (dn0 * sn0 - vn0) + 2.0 * (dn1 * sn1 - vn1);
            double NN = (double)N_ROWS * (double)N_ROWS;
            double contrast = (same + d_cross) / NN;
            double focal = focal_s / (double)N_ROWS;
            double graph = 0.1 * graph_s / (double)(N_ROWS - 1);
            out[0] = (float)(focal + contrast + graph);
            d_cross = 0.0;
            d_done  = 0u;
        }
        d_vsum[cls][comp] = 0.0f;
    }
}

// ---------------- launch ----------------
extern "C" void kernel_launch(void* const* d_in, const int* in_sizes, int n_in,
                              void* d_out, int out_size) {
    const float* preds    = (const float*)d_in[0];
    const float* targets  = (const float*)d_in[1];
    const float* features = (const float*)d_in[2];
    const float* gfeat    = (const float*)d_in[3];
    float* out = (float*)d_out;

    fused_kernel<<<GRID_TOT, 256>>>(preds, targets, features, gfeat, out);
}